// round 16
// baseline (speedup 1.0000x reference)
#include <cuda_runtime.h>
#include <cuda_fp16.h>
#include <cstdint>

#define T_TOK 4096
#define D_MODEL 1024
#define NH 16
#define QKV_N 3072

// Scratch (__device__ globals per allocation rules)
__device__ __half g_qkvh[T_TOK * QKV_N];     // q(prescaled by 0.125*log2e)|k|v
__device__ __half g_attnh[T_TOK * D_MODEL];  // attention out
__device__ __half g_xh[T_TOK * D_MODEL];
__device__ __half g_wqkvh[QKV_N * D_MODEL];
__device__ __half g_wouth[D_MODEL * D_MODEL];

// ---------------------------------------------------------------------------
// helpers
// ---------------------------------------------------------------------------
__device__ __forceinline__ void cp16(void* smem, const void* gmem) {
    uint32_t s = (uint32_t)__cvta_generic_to_shared(smem);
    asm volatile("cp.async.cg.shared.global [%0], [%1], 16;" :: "r"(s), "l"(gmem));
}
__device__ __forceinline__ void cp_commit() { asm volatile("cp.async.commit_group;"); }
template <int N> __device__ __forceinline__ void cp_wait() {
    asm volatile("cp.async.wait_group %0;" :: "n"(N));
}
__device__ __forceinline__ uint32_t pack2(float a, float b) {
    __half2 h = __floats2half2_rn(a, b);   // a -> low half
    return *reinterpret_cast<uint32_t*>(&h);
}
__device__ __forceinline__ float ex2(float x) {
    float r; asm("ex2.approx.ftz.f32 %0, %1;" : "=f"(r) : "f"(x)); return r;
}
__device__ __forceinline__ void ldsm4(uint32_t* r, uint32_t addr) {
    asm volatile("ldmatrix.sync.aligned.m8n8.x4.shared.b16 {%0,%1,%2,%3}, [%4];"
                 : "=r"(r[0]), "=r"(r[1]), "=r"(r[2]), "=r"(r[3]) : "r"(addr));
}
__device__ __forceinline__ void ldsm4t(uint32_t* r, uint32_t addr) {
    asm volatile("ldmatrix.sync.aligned.m8n8.x4.trans.shared.b16 {%0,%1,%2,%3}, [%4];"
                 : "=r"(r[0]), "=r"(r[1]), "=r"(r[2]), "=r"(r[3]) : "r"(addr));
}
__device__ __forceinline__ void mma16(float* c, const uint32_t* a, uint32_t b0, uint32_t b1) {
    asm("mma.sync.aligned.m16n8k16.row.col.f32.f16.f16.f32 "
        "{%0,%1,%2,%3}, {%4,%5,%6,%7}, {%8,%9}, {%0,%1,%2,%3};"
        : "+f"(c[0]), "+f"(c[1]), "+f"(c[2]), "+f"(c[3])
        : "r"(a[0]), "r"(a[1]), "r"(a[2]), "r"(a[3]), "r"(b0), "r"(b1));
}

// ---------------------------------------------------------------------------
// fused fp32 -> fp16 rounding for all three inputs (one launch)
// ---------------------------------------------------------------------------
__global__ void round_all(const float4* __restrict__ a, uint2* __restrict__ ao, int na,
                          const float4* __restrict__ b, uint2* __restrict__ bo, int nb,
                          const float4* __restrict__ c, uint2* __restrict__ co, int nc) {
    int i = blockIdx.x * blockDim.x + threadIdx.x;
    const float4* src;
    uint2* dst;
    if (i < na) { src = a + i; dst = ao + i; }
    else if (i < na + nb) { src = b + (i - na); dst = bo + (i - na); }
    else if (i < na + nb + nc) { src = c + (i - na - nb); dst = co + (i - na - nb); }
    else return;
    float4 v = *src;
    *dst = make_uint2(pack2(v.x, v.y), pack2(v.z, v.w));
}

// ---------------------------------------------------------------------------
// fp16 tensor-core GEMM (NT), KT=64 k-tiles, 3-stage cp.async pipeline.
// HALF_OUT: Q block (cols < 1024) pre-scaled by 0.125*log2e.
// ---------------------------------------------------------------------------
#define SAH 72
#define STG (2 * 128 * SAH)
#define GEMM_SMEM (3 * STG * 2)      // 110592 B

#define QSCALE 0.18033688011112042f  // 0.125 * log2(e)

template <bool HALF_OUT>
__global__ __launch_bounds__(256, 2) void gemm_h(const __half* __restrict__ A,
                                                 const __half* __restrict__ B,
                                                 void* __restrict__ Cv,
                                                 int M, int N, int K) {
    extern __shared__ __half smh[];
    const uint32_t sbase = (uint32_t)__cvta_generic_to_shared(smh);

    const int tid = threadIdx.x;
    const int wid = tid >> 5, lane = tid & 31;
    const int g = lane >> 2, tig = lane & 3;
    const int mW = (wid >> 2) * 64, nW = (wid & 3) * 32;
    const int by = blockIdx.y * 128, bx = blockIdx.x * 128;

    const int lr8 = (lane & 7) + ((lane >> 3) & 1) * 8;
    const int lc8 = (lane >> 4) * 8;
    const int bn8 = (lane & 7) + (lane >> 4) * 8;
    const int bk8 = ((lane >> 3) & 1) * 8;

    float acc[4][4][4];
#pragma unroll
    for (int a = 0; a < 4; a++)
#pragma unroll
        for (int b = 0; b < 4; b++)
#pragma unroll
            for (int c = 0; c < 4; c++) acc[a][b][c] = 0.f;

    const int nkt = K / 64;

    auto fill = [&](int kt, int s) {
        const __half* Ag = A + (size_t)by * K + kt * 64;
        const __half* Bg = B + (size_t)bx * K + kt * 64;
        __half* Ab = smh + s * STG;
        __half* Bb = Ab + 128 * SAH;
#pragma unroll
        for (int i = 0; i < 4; i++) {
            int e = tid + 256 * i;
            int row = e >> 3, c = (e & 7) * 8;
            cp16(&Ab[row * SAH + c], Ag + (size_t)row * K + c);
            cp16(&Bb[row * SAH + c], Bg + (size_t)row * K + c);
        }
        cp_commit();
    };

    fill(0, 0);
    if (nkt > 1) fill(1, 1);
    for (int kt = 0; kt < nkt; kt++) {
        const int s = kt % 3;
        if (kt < nkt - 1) cp_wait<1>(); else cp_wait<0>();
        __syncthreads();
        if (kt + 2 < nkt) fill(kt + 2, (kt + 2) % 3);

        const uint32_t aoff = sbase + (uint32_t)(s * STG) * 2;
        const uint32_t boff = aoff + (uint32_t)(128 * SAH) * 2;

#pragma unroll
        for (int ks = 0; ks < 4; ks++) {
            uint32_t af[4][4], bf[2][4];
#pragma unroll
            for (int mt = 0; mt < 4; mt++) {
                int r = mW + mt * 16 + lr8;
                int c = ks * 16 + lc8;
                ldsm4(af[mt], aoff + (r * SAH + c) * 2);
            }
#pragma unroll
            for (int nh = 0; nh < 2; nh++) {
                int r = nW + nh * 16 + bn8;
                int c = ks * 16 + bk8;
                ldsm4(bf[nh], boff + (r * SAH + c) * 2);
            }
#pragma unroll
            for (int mt = 0; mt < 4; mt++)
#pragma unroll
                for (int nt = 0; nt < 4; nt++)
                    mma16(acc[mt][nt], af[mt], bf[nt >> 1][(nt & 1) * 2],
                          bf[nt >> 1][(nt & 1) * 2 + 1]);
        }
    }

    const float sc = (HALF_OUT && bx < 1024) ? QSCALE : 1.f;
#pragma unroll
    for (int mt = 0; mt < 4; mt++) {
#pragma unroll
        for (int nt = 0; nt < 4; nt++) {
            int row = by + mW + mt * 16 + g;
            int col = bx + nW + nt * 8 + tig * 2;
            if (HALF_OUT) {
                __half* C = (__half*)Cv;
                *(uint32_t*)&C[(size_t)row * N + col] =
                    pack2(acc[mt][nt][0] * sc, acc[mt][nt][1] * sc);
                *(uint32_t*)&C[(size_t)(row + 8) * N + col] =
                    pack2(acc[mt][nt][2] * sc, acc[mt][nt][3] * sc);
            } else {
                float* C = (float*)Cv;
                *(float2*)&C[(size_t)row * N + col] = make_float2(acc[mt][nt][0], acc[mt][nt][1]);
                *(float2*)&C[(size_t)(row + 8) * N + col] = make_float2(acc[mt][nt][2], acc[mt][nt][3]);
            }
        }
    }
}

// ---------------------------------------------------------------------------
// fp16 causal attention v4: 256 Q-rows per block, 8 warps x 32 rows.
// Halves K/V traffic + barriers per mma; 16 warps/SM at occupancy 2.
// Q pre-scaled by 0.125*log2e -> p = ex2(s). fp32 lsum on FMA pipe.
// ---------------------------------------------------------------------------
#define KS 72
#define KVSTG (2 * 64 * KS)
#define QROWS 256
#define ATT_SMEM ((QROWS * KS + 3 * KVSTG) * 2)   // 92160 B

__global__ __launch_bounds__(256, 2) void attn_h(const __half* __restrict__ qkv,
                                                 __half* __restrict__ outp) {
    extern __shared__ __half smh[];
    __half* Qs = smh;
    const uint32_t sbase = (uint32_t)__cvta_generic_to_shared(smh);
    const uint32_t qoff = sbase;

    const int h = blockIdx.y;
    const int qb = gridDim.x - 1 - blockIdx.x;         // heavy tiles first
    const int q0 = qb * QROWS;
    const int tid = threadIdx.x;
    const int wid = tid >> 5, lane = tid & 31;
    const int g = lane >> 2, tig = lane & 3;
    const int mrow = wid * 32;
    const int nkb = 4 * qb + 4;                        // 64-key tiles

    const int lr8 = (lane & 7) + ((lane >> 3) & 1) * 8;
    const int lc8 = (lane >> 4) * 8;
    const int bn8 = (lane & 7) + (lane >> 4) * 8;
    const int bk8 = ((lane >> 3) & 1) * 8;

    auto load_kv = [&](int kb, int s) {
        const int k0 = kb * 64;
        __half* Kb = smh + QROWS * KS + s * KVSTG;
        __half* Vb = Kb + 64 * KS;
#pragma unroll
        for (int i = 0; i < 2; i++) {                  // 512 chunks each
            int e = tid + 256 * i;
            int row = e >> 3, c = (e & 7) * 8;
            size_t base = (size_t)(k0 + row) * QKV_N + h * 64 + c;
            cp16(&Kb[row * KS + c], &qkv[base + 1024]);
            cp16(&Vb[row * KS + c], &qkv[base + 2048]);
        }
        cp_commit();
    };

    // Q (256x64) + KV(0) in one group; KV(1) second group
#pragma unroll
    for (int i = 0; i < 8; i++) {                      // 2048 chunks
        int e = tid + 256 * i;
        int row = e >> 3, c = (e & 7) * 8;
        cp16(&Qs[row * KS + c], &qkv[(size_t)(q0 + row) * QKV_N + h * 64 + c]);
    }
    load_kv(0, 0);
    load_kv(1, 1);

    float oacc[2][8][4];
#pragma unroll
    for (int hh = 0; hh < 2; hh++)
#pragma unroll
        for (int a = 0; a < 8; a++)
#pragma unroll
            for (int c = 0; c < 4; c++) oacc[hh][a][c] = 0.f;
    float lsum[2][2] = {{0.f, 0.f}, {0.f, 0.f}};

    for (int kb = 0; kb < nkb; kb++) {
        const int s = kb % 3;
        if (kb < nkb - 1) cp_wait<1>(); else cp_wait<0>();
        __syncthreads();
        if (kb + 2 < nkb) load_kv(kb + 2, (kb + 2) % 3);

        const uint32_t koff = sbase + (uint32_t)(QROWS * KS + s * KVSTG) * 2;
        const uint32_t voff = koff + (uint32_t)(64 * KS) * 2;

        // ---- S = Q K^T (s already in log2 units) ----
        float sacc[2][8][4];
#pragma unroll
        for (int hh = 0; hh < 2; hh++)
#pragma unroll
            for (int a = 0; a < 8; a++)
#pragma unroll
                for (int c = 0; c < 4; c++) sacc[hh][a][c] = 0.f;

#pragma unroll
        for (int ks = 0; ks < 4; ks++) {
            uint32_t aq[2][4];
            ldsm4(aq[0], qoff + ((mrow + lr8) * KS + ks * 16 + lc8) * 2);
            ldsm4(aq[1], qoff + ((mrow + 16 + lr8) * KS + ks * 16 + lc8) * 2);
#pragma unroll
            for (int nh = 0; nh < 4; nh++) {
                uint32_t bf[4];
                ldsm4(bf, koff + ((nh * 16 + bn8) * KS + ks * 16 + bk8) * 2);
#pragma unroll
                for (int hh = 0; hh < 2; hh++) {
                    mma16(sacc[hh][nh * 2 + 0], aq[hh], bf[0], bf[1]);
                    mma16(sacc[hh][nh * 2 + 1], aq[hh], bf[2], bf[3]);
                }
            }
        }

        // ---- softmax numerator: p = ex2(s); mask; fp32 lsum; pack ----
        const int k0 = kb * 64;
        const bool diag = (kb >= 4 * qb);              // partially masked tiles
        uint32_t pfrag[2][4][4];
#pragma unroll
        for (int hh = 0; hh < 2; hh++) {
#pragma unroll
            for (int nt = 0; nt < 8; nt++) {
                float p0 = ex2(sacc[hh][nt][0]);
                float p1 = ex2(sacc[hh][nt][1]);
                float p2 = ex2(sacc[hh][nt][2]);
                float p3 = ex2(sacc[hh][nt][3]);
                if (diag) {
                    int row0 = q0 + mrow + hh * 16 + g;
                    int c0 = k0 + nt * 8 + 2 * tig;
                    if (c0 > row0) p0 = 0.f;
                    if (c0 + 1 > row0) p1 = 0.f;
                    if (c0 > row0 + 8) p2 = 0.f;
                    if (c0 + 1 > row0 + 8) p3 = 0.f;
                }
                lsum[hh][0] += p0 + p1;
                lsum[hh][1] += p2 + p3;
                pfrag[hh][nt >> 1][(nt & 1) * 2 + 0] = pack2(p0, p1);
                pfrag[hh][nt >> 1][(nt & 1) * 2 + 1] = pack2(p2, p3);
            }
        }

        // ---- O += P V ----
#pragma unroll
        for (int ksp = 0; ksp < 4; ksp++) {
#pragma unroll
            for (int dh = 0; dh < 4; dh++) {
                uint32_t bf[4];
                ldsm4t(bf, voff + ((ksp * 16 + lr8) * KS + dh * 16 + lc8) * 2);
#pragma unroll
                for (int hh = 0; hh < 2; hh++) {
                    mma16(oacc[hh][dh * 2 + 0], pfrag[hh][ksp], bf[0], bf[1]);
                    mma16(oacc[hh][dh * 2 + 1], pfrag[hh][ksp], bf[2], bf[3]);
                }
            }
        }
    }

    // ---- quad row-sum reduction, normalize, fp16 store ----
#pragma unroll
    for (int hh = 0; hh < 2; hh++)
#pragma unroll
        for (int e = 0; e < 2; e++) {
            lsum[hh][e] += __shfl_xor_sync(0xffffffffu, lsum[hh][e], 1);
            lsum[hh][e] += __shfl_xor_sync(0xffffffffu, lsum[hh][e], 2);
        }

#pragma unroll
    for (int hh = 0; hh < 2; hh++) {
        float inv0 = 1.f / lsum[hh][0];
        float inv1 = 1.f / lsum[hh][1];
#pragma unroll
        for (int nt = 0; nt < 8; nt++) {
            int col = h * 64 + nt * 8 + 2 * tig;
            int row0 = q0 + mrow + hh * 16 + g;
            *(uint32_t*)&outp[(size_t)row0 * D_MODEL + col] =
                pack2(oacc[hh][nt][0] * inv0, oacc[hh][nt][1] * inv0);
            *(uint32_t*)&outp[(size_t)(row0 + 8) * D_MODEL + col] =
                pack2(oacc[hh][nt][2] * inv1, oacc[hh][nt][3] * inv1);
        }
    }
}

// ---------------------------------------------------------------------------
// Launch
// ---------------------------------------------------------------------------
extern "C" void kernel_launch(void* const* d_in, const int* in_sizes, int n_in,
                              void* d_out, int out_size) {
    const float* x    = (const float*)d_in[0];   // [4096,1024]
    const float* Wqkv = (const float*)d_in[1];   // [3072,1024]
    const float* Wout = (const float*)d_in[2];   // [1024,1024]
    float* out = (float*)d_out;                  // [4096,1024]

    __half *qkvh, *attnh, *xh, *wqkvh, *wouth;
    cudaGetSymbolAddress((void**)&qkvh, g_qkvh);
    cudaGetSymbolAddress((void**)&attnh, g_attnh);
    cudaGetSymbolAddress((void**)&xh, g_xh);
    cudaGetSymbolAddress((void**)&wqkvh, g_wqkvh);
    cudaGetSymbolAddress((void**)&wouth, g_wouth);

    cudaFuncSetAttribute(gemm_h<true>, cudaFuncAttributeMaxDynamicSharedMemorySize, GEMM_SMEM);
    cudaFuncSetAttribute(gemm_h<false>, cudaFuncAttributeMaxDynamicSharedMemorySize, GEMM_SMEM);
    cudaFuncSetAttribute(attn_h, cudaFuncAttributeMaxDynamicSharedMemorySize, ATT_SMEM);

    // 0) all inputs -> fp16 (single launch)
    const int na = T_TOK * D_MODEL / 4, nb = QKV_N * D_MODEL / 4, nc = D_MODEL * D_MODEL / 4;
    round_all<<<(na + nb + nc + 255) / 256, 256>>>(
        (const float4*)x, (uint2*)xh, na,
        (const float4*)Wqkv, (uint2*)wqkvh, nb,
        (const float4*)Wout, (uint2*)wouth, nc);

    // 1) QKV projection (Q block pre-scaled by 0.125*log2e in epilogue)
    gemm_h<true><<<dim3(QKV_N / 128, T_TOK / 128), 256, GEMM_SMEM>>>(
        xh, wqkvh, qkvh, T_TOK, QKV_N, D_MODEL);

    // 2) causal clamped attention (256-row Q tiles)
    attn_h<<<dim3(T_TOK / QROWS, NH), 256, ATT_SMEM>>>(qkvh, attnh);

    // 3) output projection (fp32 out)
    gemm_h<false><<<dim3(D_MODEL / 128, T_TOK / 128), 256, GEMM_SMEM>>>(
        attnh, wouth, out, T_TOK, D_MODEL, D_MODEL);
}

// round 17
// speedup vs baseline: 1.2671x; 1.2671x over previous
#include <cuda_runtime.h>
#include <cuda_fp16.h>
#include <cstdint>

#define T_TOK 4096
#define D_MODEL 1024
#define NH 16
#define QKV_N 3072

// Scratch (__device__ globals per allocation rules)
__device__ __half g_qkvh[T_TOK * QKV_N];     // q(prescaled by 0.125*log2e)|k|v
__device__ __half g_attnh[T_TOK * D_MODEL];  // attention out
__device__ __half g_xh[T_TOK * D_MODEL];
__device__ __half g_wqkvh[QKV_N * D_MODEL];
__device__ __half g_wouth[D_MODEL * D_MODEL];

// ---------------------------------------------------------------------------
// helpers
// ---------------------------------------------------------------------------
__device__ __forceinline__ void cp16(void* smem, const void* gmem) {
    uint32_t s = (uint32_t)__cvta_generic_to_shared(smem);
    asm volatile("cp.async.cg.shared.global [%0], [%1], 16;" :: "r"(s), "l"(gmem));
}
__device__ __forceinline__ void cp_commit() { asm volatile("cp.async.commit_group;"); }
template <int N> __device__ __forceinline__ void cp_wait() {
    asm volatile("cp.async.wait_group %0;" :: "n"(N));
}
__device__ __forceinline__ uint32_t pack2(float a, float b) {
    __half2 h = __floats2half2_rn(a, b);   // a -> low half
    return *reinterpret_cast<uint32_t*>(&h);
}
__device__ __forceinline__ float ex2(float x) {
    float r; asm("ex2.approx.ftz.f32 %0, %1;" : "=f"(r) : "f"(x)); return r;
}
__device__ __forceinline__ void ldsm4(uint32_t* r, uint32_t addr) {
    asm volatile("ldmatrix.sync.aligned.m8n8.x4.shared.b16 {%0,%1,%2,%3}, [%4];"
                 : "=r"(r[0]), "=r"(r[1]), "=r"(r[2]), "=r"(r[3]) : "r"(addr));
}
__device__ __forceinline__ void ldsm4t(uint32_t* r, uint32_t addr) {
    asm volatile("ldmatrix.sync.aligned.m8n8.x4.trans.shared.b16 {%0,%1,%2,%3}, [%4];"
                 : "=r"(r[0]), "=r"(r[1]), "=r"(r[2]), "=r"(r[3]) : "r"(addr));
}
__device__ __forceinline__ void mma16(float* c, const uint32_t* a, uint32_t b0, uint32_t b1) {
    asm("mma.sync.aligned.m16n8k16.row.col.f32.f16.f16.f32 "
        "{%0,%1,%2,%3}, {%4,%5,%6,%7}, {%8,%9}, {%0,%1,%2,%3};"
        : "+f"(c[0]), "+f"(c[1]), "+f"(c[2]), "+f"(c[3])
        : "r"(a[0]), "r"(a[1]), "r"(a[2]), "r"(a[3]), "r"(b0), "r"(b1));
}

// ---------------------------------------------------------------------------
// fused fp32 -> fp16 rounding for all three inputs (one launch)
// ---------------------------------------------------------------------------
__global__ void round_all(const float4* __restrict__ a, uint2* __restrict__ ao, int na,
                          const float4* __restrict__ b, uint2* __restrict__ bo, int nb,
                          const float4* __restrict__ c, uint2* __restrict__ co, int nc) {
    int i = blockIdx.x * blockDim.x + threadIdx.x;
    const float4* src;
    uint2* dst;
    if (i < na) { src = a + i; dst = ao + i; }
    else if (i < na + nb) { src = b + (i - na); dst = bo + (i - na); }
    else if (i < na + nb + nc) { src = c + (i - na - nb); dst = co + (i - na - nb); }
    else return;
    float4 v = *src;
    *dst = make_uint2(pack2(v.x, v.y), pack2(v.z, v.w));
}

// ---------------------------------------------------------------------------
// fp16 tensor-core GEMM (NT), KT=64 k-tiles, 3-stage cp.async pipeline.
// HALF_OUT: Q block (cols < 1024) pre-scaled by 0.125*log2e so attention
// scores come out of the mma directly in log2 units.
// ---------------------------------------------------------------------------
#define SAH 72                       // 64 data halves + 8 pad (144B rows)
#define STG (2 * 128 * SAH)          // halves per stage (A then B)
#define GEMM_SMEM (3 * STG * 2)      // 110592 B

#define QSCALE 0.18033688011112042f  // 0.125 * log2(e)

template <bool HALF_OUT>
__global__ __launch_bounds__(256, 2) void gemm_h(const __half* __restrict__ A,
                                                 const __half* __restrict__ B,
                                                 void* __restrict__ Cv,
                                                 int M, int N, int K) {
    extern __shared__ __half smh[];
    const uint32_t sbase = (uint32_t)__cvta_generic_to_shared(smh);

    const int tid = threadIdx.x;
    const int wid = tid >> 5, lane = tid & 31;
    const int g = lane >> 2, tig = lane & 3;
    const int mW = (wid >> 2) * 64, nW = (wid & 3) * 32;
    const int by = blockIdx.y * 128, bx = blockIdx.x * 128;

    const int lr8 = (lane & 7) + ((lane >> 3) & 1) * 8;
    const int lc8 = (lane >> 4) * 8;
    const int bn8 = (lane & 7) + (lane >> 4) * 8;
    const int bk8 = ((lane >> 3) & 1) * 8;

    float acc[4][4][4];
#pragma unroll
    for (int a = 0; a < 4; a++)
#pragma unroll
        for (int b = 0; b < 4; b++)
#pragma unroll
            for (int c = 0; c < 4; c++) acc[a][b][c] = 0.f;

    const int nkt = K / 64;

    auto fill = [&](int kt, int s) {
        const __half* Ag = A + (size_t)by * K + kt * 64;
        const __half* Bg = B + (size_t)bx * K + kt * 64;
        __half* Ab = smh + s * STG;
        __half* Bb = Ab + 128 * SAH;
#pragma unroll
        for (int i = 0; i < 4; i++) {
            int e = tid + 256 * i;
            int row = e >> 3, c = (e & 7) * 8;
            cp16(&Ab[row * SAH + c], Ag + (size_t)row * K + c);
            cp16(&Bb[row * SAH + c], Bg + (size_t)row * K + c);
        }
        cp_commit();
    };

    fill(0, 0);
    if (nkt > 1) fill(1, 1);
    for (int kt = 0; kt < nkt; kt++) {
        const int s = kt % 3;
        if (kt < nkt - 1) cp_wait<1>(); else cp_wait<0>();
        __syncthreads();
        if (kt + 2 < nkt) fill(kt + 2, (kt + 2) % 3);

        const uint32_t aoff = sbase + (uint32_t)(s * STG) * 2;
        const uint32_t boff = aoff + (uint32_t)(128 * SAH) * 2;

#pragma unroll
        for (int ks = 0; ks < 4; ks++) {
            uint32_t af[4][4], bf[2][4];
#pragma unroll
            for (int mt = 0; mt < 4; mt++) {
                int r = mW + mt * 16 + lr8;
                int c = ks * 16 + lc8;
                ldsm4(af[mt], aoff + (r * SAH + c) * 2);
            }
#pragma unroll
            for (int nh = 0; nh < 2; nh++) {
                int r = nW + nh * 16 + bn8;
                int c = ks * 16 + bk8;
                ldsm4(bf[nh], boff + (r * SAH + c) * 2);
            }
#pragma unroll
            for (int mt = 0; mt < 4; mt++)
#pragma unroll
                for (int nt = 0; nt < 4; nt++)
                    mma16(acc[mt][nt], af[mt], bf[nt >> 1][(nt & 1) * 2],
                          bf[nt >> 1][(nt & 1) * 2 + 1]);
        }
    }

    const float sc = (HALF_OUT && bx < 1024) ? QSCALE : 1.f;
#pragma unroll
    for (int mt = 0; mt < 4; mt++) {
#pragma unroll
        for (int nt = 0; nt < 4; nt++) {
            int row = by + mW + mt * 16 + g;
            int col = bx + nW + nt * 8 + tig * 2;
            if (HALF_OUT) {
                __half* C = (__half*)Cv;
                *(uint32_t*)&C[(size_t)row * N + col] =
                    pack2(acc[mt][nt][0] * sc, acc[mt][nt][1] * sc);
                *(uint32_t*)&C[(size_t)(row + 8) * N + col] =
                    pack2(acc[mt][nt][2] * sc, acc[mt][nt][3] * sc);
            } else {
                float* C = (float*)Cv;
                *(float2*)&C[(size_t)row * N + col] = make_float2(acc[mt][nt][0], acc[mt][nt][1]);
                *(float2*)&C[(size_t)(row + 8) * N + col] = make_float2(acc[mt][nt][2], acc[mt][nt][3]);
            }
        }
    }
}

// ---------------------------------------------------------------------------
// fp16 causal attention (PROVEN R15 config: 128-row Q tiles, 4 warps x 32
// rows, occ 3, 3-stage K/V pipeline). Q pre-scaled by 0.125*log2e ->
// softmax numerator is just p = ex2(s). fp32 lsum on FMA pipe.
// ---------------------------------------------------------------------------
#define KS 72
#define KVSTG (2 * 64 * KS)
#define ATT_SMEM ((128 * KS + 3 * KVSTG) * 2)   // 73728 B

__global__ __launch_bounds__(128, 3) void attn_h(const __half* __restrict__ qkv,
                                                 __half* __restrict__ outp) {
    extern __shared__ __half smh[];
    __half* Qs = smh;
    const uint32_t sbase = (uint32_t)__cvta_generic_to_shared(smh);
    const uint32_t qoff = sbase;

    const int h = blockIdx.y;
    const int qb = gridDim.x - 1 - blockIdx.x;         // heavy tiles first
    const int q0 = qb * 128;
    const int tid = threadIdx.x;
    const int wid = tid >> 5, lane = tid & 31;
    const int g = lane >> 2, tig = lane & 3;
    const int mrow = wid * 32;
    const int nkb = 2 * qb + 2;

    const int lr8 = (lane & 7) + ((lane >> 3) & 1) * 8;
    const int lc8 = (lane >> 4) * 8;
    const int bn8 = (lane & 7) + (lane >> 4) * 8;
    const int bk8 = ((lane >> 3) & 1) * 8;

    auto load_kv = [&](int kb, int s) {
        const int k0 = kb * 64;
        __half* Kb = smh + 128 * KS + s * KVSTG;
        __half* Vb = Kb + 64 * KS;
#pragma unroll
        for (int i = 0; i < 4; i++) {
            int e = tid + 128 * i;
            int row = e >> 3, c = (e & 7) * 8;
            size_t base = (size_t)(k0 + row) * QKV_N + h * 64 + c;
            cp16(&Kb[row * KS + c], &qkv[base + 1024]);
            cp16(&Vb[row * KS + c], &qkv[base + 2048]);
        }
        cp_commit();
    };

#pragma unroll
    for (int i = 0; i < 8; i++) {
        int e = tid + 128 * i;
        int row = e >> 3, c = (e & 7) * 8;
        cp16(&Qs[row * KS + c], &qkv[(size_t)(q0 + row) * QKV_N + h * 64 + c]);
    }
    load_kv(0, 0);
    load_kv(1, 1);

    float oacc[2][8][4];
#pragma unroll
    for (int hh = 0; hh < 2; hh++)
#pragma unroll
        for (int a = 0; a < 8; a++)
#pragma unroll
            for (int c = 0; c < 4; c++) oacc[hh][a][c] = 0.f;
    float lsum[2][2] = {{0.f, 0.f}, {0.f, 0.f}};

    for (int kb = 0; kb < nkb; kb++) {
        const int s = kb % 3;
        if (kb < nkb - 1) cp_wait<1>(); else cp_wait<0>();
        __syncthreads();
        if (kb + 2 < nkb) load_kv(kb + 2, (kb + 2) % 3);

        const uint32_t koff = sbase + (uint32_t)(128 * KS + s * KVSTG) * 2;
        const uint32_t voff = koff + (uint32_t)(64 * KS) * 2;

        // ---- S = Q K^T (Q pre-scaled; s already in log2 units) ----
        float sacc[2][8][4];
#pragma unroll
        for (int hh = 0; hh < 2; hh++)
#pragma unroll
            for (int a = 0; a < 8; a++)
#pragma unroll
                for (int c = 0; c < 4; c++) sacc[hh][a][c] = 0.f;

#pragma unroll
        for (int ks = 0; ks < 4; ks++) {
            uint32_t aq[2][4];
            ldsm4(aq[0], qoff + ((mrow + lr8) * KS + ks * 16 + lc8) * 2);
            ldsm4(aq[1], qoff + ((mrow + 16 + lr8) * KS + ks * 16 + lc8) * 2);
#pragma unroll
            for (int nh = 0; nh < 4; nh++) {
                uint32_t bf[4];
                ldsm4(bf, koff + ((nh * 16 + bn8) * KS + ks * 16 + bk8) * 2);
#pragma unroll
                for (int hh = 0; hh < 2; hh++) {
                    mma16(sacc[hh][nh * 2 + 0], aq[hh], bf[0], bf[1]);
                    mma16(sacc[hh][nh * 2 + 1], aq[hh], bf[2], bf[3]);
                }
            }
        }

        // ---- softmax numerator: p = ex2(s); mask; fp32 lsum; pack ----
        const int k0 = kb * 64;
        const bool diag = (kb >= 2 * qb);
        uint32_t pfrag[2][4][4];
#pragma unroll
        for (int hh = 0; hh < 2; hh++) {
#pragma unroll
            for (int nt = 0; nt < 8; nt++) {
                float p0 = ex2(sacc[hh][nt][0]);
                float p1 = ex2(sacc[hh][nt][1]);
                float p2 = ex2(sacc[hh][nt][2]);
                float p3 = ex2(sacc[hh][nt][3]);
                if (diag) {
                    int row0 = q0 + mrow + hh * 16 + g;
                    int c0 = k0 + nt * 8 + 2 * tig;
                    if (c0 > row0) p0 = 0.f;
                    if (c0 + 1 > row0) p1 = 0.f;
                    if (c0 > row0 + 8) p2 = 0.f;
                    if (c0 + 1 > row0 + 8) p3 = 0.f;
                }
                lsum[hh][0] += p0 + p1;
                lsum[hh][1] += p2 + p3;
                pfrag[hh][nt >> 1][(nt & 1) * 2 + 0] = pack2(p0, p1);
                pfrag[hh][nt >> 1][(nt & 1) * 2 + 1] = pack2(p2, p3);
            }
        }

        // ---- O += P V ----
#pragma unroll
        for (int ksp = 0; ksp < 4; ksp++) {
#pragma unroll
            for (int dh = 0; dh < 4; dh++) {
                uint32_t bf[4];
                ldsm4t(bf, voff + ((ksp * 16 + lr8) * KS + dh * 16 + lc8) * 2);
#pragma unroll
                for (int hh = 0; hh < 2; hh++) {
                    mma16(oacc[hh][dh * 2 + 0], pfrag[hh][ksp], bf[0], bf[1]);
                    mma16(oacc[hh][dh * 2 + 1], pfrag[hh][ksp], bf[2], bf[3]);
                }
            }
        }
    }

    // ---- quad row-sum reduction, normalize, fp16 store ----
#pragma unroll
    for (int hh = 0; hh < 2; hh++)
#pragma unroll
        for (int e = 0; e < 2; e++) {
            lsum[hh][e] += __shfl_xor_sync(0xffffffffu, lsum[hh][e], 1);
            lsum[hh][e] += __shfl_xor_sync(0xffffffffu, lsum[hh][e], 2);
        }

#pragma unroll
    for (int hh = 0; hh < 2; hh++) {
        float inv0 = 1.f / lsum[hh][0];
        float inv1 = 1.f / lsum[hh][1];
#pragma unroll
        for (int nt = 0; nt < 8; nt++) {
            int col = h * 64 + nt * 8 + 2 * tig;
            int row0 = q0 + mrow + hh * 16 + g;
            *(uint32_t*)&outp[(size_t)row0 * D_MODEL + col] =
                pack2(oacc[hh][nt][0] * inv0, oacc[hh][nt][1] * inv0);
            *(uint32_t*)&outp[(size_t)(row0 + 8) * D_MODEL + col] =
                pack2(oacc[hh][nt][2] * inv1, oacc[hh][nt][3] * inv1);
        }
    }
}

// ---------------------------------------------------------------------------
// Launch
// ---------------------------------------------------------------------------
extern "C" void kernel_launch(void* const* d_in, const int* in_sizes, int n_in,
                              void* d_out, int out_size) {
    const float* x    = (const float*)d_in[0];   // [4096,1024]
    const float* Wqkv = (const float*)d_in[1];   // [3072,1024]
    const float* Wout = (const float*)d_in[2];   // [1024,1024]
    float* out = (float*)d_out;                  // [4096,1024]

    __half *qkvh, *attnh, *xh, *wqkvh, *wouth;
    cudaGetSymbolAddress((void**)&qkvh, g_qkvh);
    cudaGetSymbolAddress((void**)&attnh, g_attnh);
    cudaGetSymbolAddress((void**)&xh, g_xh);
    cudaGetSymbolAddress((void**)&wqkvh, g_wqkvh);
    cudaGetSymbolAddress((void**)&wouth, g_wouth);

    cudaFuncSetAttribute(gemm_h<true>, cudaFuncAttributeMaxDynamicSharedMemorySize, GEMM_SMEM);
    cudaFuncSetAttribute(gemm_h<false>, cudaFuncAttributeMaxDynamicSharedMemorySize, GEMM_SMEM);
    cudaFuncSetAttribute(attn_h, cudaFuncAttributeMaxDynamicSharedMemorySize, ATT_SMEM);

    // 0) all inputs -> fp16 (single launch)
    const int na = T_TOK * D_MODEL / 4, nb = QKV_N * D_MODEL / 4, nc = D_MODEL * D_MODEL / 4;
    round_all<<<(na + nb + nc + 255) / 256, 256>>>(
        (const float4*)x, (uint2*)xh, na,
        (const float4*)Wqkv, (uint2*)wqkvh, nb,
        (const float4*)Wout, (uint2*)wouth, nc);

    // 1) QKV projection (Q block pre-scaled by 0.125*log2e in epilogue)
    gemm_h<true><<<dim3(QKV_N / 128, T_TOK / 128), 256, GEMM_SMEM>>>(
        xh, wqkvh, qkvh, T_TOK, QKV_N, D_MODEL);

    // 2) causal clamped attention (128-row Q tiles, proven config)
    attn_h<<<dim3(T_TOK / 128, NH), 128, ATT_SMEM>>>(qkvh, attnh);

    // 3) output projection (fp32 out)
    gemm_h<false><<<dim3(D_MODEL / 128, T_TOK / 128), 256, GEMM_SMEM>>>(
        attnh, wouth, out, T_TOK, D_MODEL, D_MODEL);
}